// round 8
// baseline (speedup 1.0000x reference)
#include <cuda_runtime.h>

// Shapes (fixed per reference setup_inputs)
#define L_DIM 4
#define B_DIM 8
#define C_DIM 256
#define HW 4096                 // 64*64 spatial
#define QROW (HW / 4)           // 1024 float4 per row
#define NROWS (L_DIM * B_DIM * C_DIM)   // 8192

#define NCHUNK 4                // chunks of 2 batches; 2048 rows = 32 MiB each
#define CBLOCKS 1024            // blocks per chunk (2 rows per block)

// Scratch (no allocations allowed)
__device__ float g_gap[NROWS];

__device__ __forceinline__ float sum4(float4 v) { return (v.x + v.y) + (v.z + v.w); }

// chunk-local block index j (0..1023) -> first of 2 consecutive rows
// rows of chunk: l in 0..3, b in {b_base, b_base+1}, c in 0..255
__device__ __forceinline__ int chunk_row(int j, int b_base) {
    const int idx = 2 * j;                 // 0..2046, even
    const int l   = idx >> 9;              // /512
    const int rem = idx & 511;
    const int b   = b_base + (rem >> 8);
    const int c   = rem & 255;             // even; row+1 = same l,b, c+1
    return l * (B_DIM * C_DIM) + b * C_DIM + c;
}

// ---------------------------------------------------------------------------
// Kernel 1: GAP over one chunk — 2 rows per block, 8 front-loaded LDG.128
// ---------------------------------------------------------------------------
__global__ __launch_bounds__(256) void gap_kernel(const float4* __restrict__ in4,
                                                  int b_base) {
    const int r0 = chunk_row(blockIdx.x, b_base);
    const int r1 = r0 + 1;
    const float4* p0 = in4 + (size_t)r0 * QROW;
    const float4* p1 = in4 + (size_t)r1 * QROW;
    const int t = threadIdx.x;

    float4 a0 = p0[t], a1 = p0[t + 256], a2 = p0[t + 512], a3 = p0[t + 768];
    float4 b0 = p1[t], b1 = p1[t + 256], b2 = p1[t + 512], b3 = p1[t + 768];

    float sA = sum4(a0) + sum4(a1) + sum4(a2) + sum4(a3);
    float sB = sum4(b0) + sum4(b1) + sum4(b2) + sum4(b3);

    #pragma unroll
    for (int off = 16; off > 0; off >>= 1) {
        sA += __shfl_xor_sync(0xffffffffu, sA, off);
        sB += __shfl_xor_sync(0xffffffffu, sB, off);
    }

    __shared__ float wsum[2][8];
    if ((t & 31) == 0) {
        wsum[0][t >> 5] = sA;
        wsum[1][t >> 5] = sB;
    }
    __syncthreads();

    if (t < 2) {
        float r = 0.f;
        #pragma unroll
        for (int k = 0; k < 8; k++) r += wsum[t][k];
        g_gap[r0 + t] = r * (1.0f / (float)HW);
    }
}

// ---------------------------------------------------------------------------
// Kernel 2 (fused): per-block attn recompute + scale + store, one chunk.
// Reverse traversal within the chunk (freshest L2 lines from gap first).
// Loads default policy; stores default write-back (proven fastest).
// ---------------------------------------------------------------------------
__global__ __launch_bounds__(256) void scale_kernel(const float4* __restrict__ in4,
                                                    const float*  __restrict__ Wlin,
                                                    float4* __restrict__ out4,
                                                    int b_base) {
    const int r0 = chunk_row((CBLOCKS - 1) - blockIdx.x, b_base);
    const int r1 = r0 + 1;
    const float4* p0 = in4 + (size_t)r0 * QROW;
    const float4* p1 = in4 + (size_t)r1 * QROW;
    float4* q0 = out4 + (size_t)r0 * QROW;
    float4* q1 = out4 + (size_t)r1 * QROW;
    const int t = threadIdx.x;

    // ---- issue the 8 big loads first ----
    float4 v0 = p0[t];
    float4 v1 = p0[t + 256];
    float4 v2 = p0[t + 512];
    float4 v3 = p0[t + 768];
    float4 w0 = p1[t];
    float4 w1 = p1[t + 256];
    float4 w2 = p1[t + 512];
    float4 w3 = p1[t + 768];

    // ---- attn prologue (overlaps with loads in flight) ----
    // row = l*2048 + b*256 + d
    const int l0 = r0 >> 11, b0i = (r0 >> 8) & 7, d0 = r0 & 255;
    const int l1 = r1 >> 11, b1i = (r1 >> 8) & 7, d1 = r1 & 255;

    const float wtA = __ldg(&Wlin[d0 * C_DIM + t]);
    const float wtB = __ldg(&Wlin[d1 * C_DIM + t]);

    float s[8];
    #pragma unroll
    for (int l = 0; l < L_DIM; l++) {
        s[l]     = __ldg(&g_gap[l * (B_DIM * C_DIM) + b0i * C_DIM + t]) * wtA;
        s[4 + l] = __ldg(&g_gap[l * (B_DIM * C_DIM) + b1i * C_DIM + t]) * wtB;
    }
    #pragma unroll
    for (int k = 0; k < 8; k++) {
        #pragma unroll
        for (int off = 16; off > 0; off >>= 1)
            s[k] += __shfl_xor_sync(0xffffffffu, s[k], off);
    }

    __shared__ float red[8][8];     // [score][warp]
    __shared__ float attn_bc[2];
    if ((t & 31) == 0) {
        #pragma unroll
        for (int k = 0; k < 8; k++) red[k][t >> 5] = s[k];
    }
    __syncthreads();
    if (t < 8) {
        float r = 0.f;
        #pragma unroll
        for (int k = 0; k < 8; k++) r += red[t][k];
        red[t][0] = r;              // reduced score t (rowA: 0-3, rowB: 4-7)
    }
    __syncthreads();
    if (t == 0) {
        float sc0 = red[0][0], sc1 = red[1][0], sc2 = red[2][0], sc3 = red[3][0];
        float m = fmaxf(fmaxf(sc0, sc1), fmaxf(sc2, sc3));
        float e0 = __expf(sc0 - m), e1 = __expf(sc1 - m);
        float e2 = __expf(sc2 - m), e3 = __expf(sc3 - m);
        float inv = 1.0f / (e0 + e1 + e2 + e3);
        float eA[4] = {e0, e1, e2, e3};
        attn_bc[0] = eA[l0] * inv;

        float t0 = red[4][0], t1 = red[5][0], t2 = red[6][0], t3 = red[7][0];
        float mB = fmaxf(fmaxf(t0, t1), fmaxf(t2, t3));
        float f0 = __expf(t0 - mB), f1 = __expf(t1 - mB);
        float f2 = __expf(t2 - mB), f3 = __expf(t3 - mB);
        float invB = 1.0f / (f0 + f1 + f2 + f3);
        float eB[4] = {f0, f1, f2, f3};
        attn_bc[1] = eB[l1] * invB;
    }
    __syncthreads();
    const float a0 = attn_bc[0];
    const float a1 = attn_bc[1];

    // ---- multiply + store (default write-back) ----
    v0.x *= a0; v0.y *= a0; v0.z *= a0; v0.w *= a0;
    v1.x *= a0; v1.y *= a0; v1.z *= a0; v1.w *= a0;
    v2.x *= a0; v2.y *= a0; v2.z *= a0; v2.w *= a0;
    v3.x *= a0; v3.y *= a0; v3.z *= a0; v3.w *= a0;
    w0.x *= a1; w0.y *= a1; w0.z *= a1; w0.w *= a1;
    w1.x *= a1; w1.y *= a1; w1.z *= a1; w1.w *= a1;
    w2.x *= a1; w2.y *= a1; w2.z *= a1; w2.w *= a1;
    w3.x *= a1; w3.y *= a1; w3.z *= a1; w3.w *= a1;

    q0[t]       = v0;
    q0[t + 256] = v1;
    q0[t + 512] = v2;
    q0[t + 768] = v3;
    q1[t]       = w0;
    q1[t + 256] = w1;
    q1[t + 512] = w2;
    q1[t + 768] = w3;
}

// ---------------------------------------------------------------------------
extern "C" void kernel_launch(void* const* d_in, const int* in_sizes, int n_in,
                              void* d_out, int out_size) {
    const float4* in4  = (const float4*)d_in[0];
    const float*  Wlin = (const float*)d_in[1];
    float4*       out4 = (float4*)d_out;

    // Interleave gap/scale per 2-batch chunk so the scale re-read finds its
    // 32 MiB chunk resident in L2 (chunk + write stream = 64 MiB << 126 MB L2).
    for (int ci = 0; ci < NCHUNK; ci++) {
        gap_kernel<<<CBLOCKS, 256>>>(in4, 2 * ci);
        scale_kernel<<<CBLOCKS, 256>>>(in4, Wlin, out4, 2 * ci);
    }
}